// round 1
// baseline (speedup 1.0000x reference)
#include <cuda_runtime.h>
#include <math.h>

#define NSTREAM 2
#define BB 2
#define NN 4096
#define CC 256
#define NH 8
#define DH 32
#define MM 1024

// ---------------- scratch (static device globals; no allocation) ----------------
__device__ float g_WqT[CC * CC];              // [k][o]
__device__ float g_WkvT[CC * 2 * CC];         // [k][o], ldb=512
__device__ float g_WprojT[CC * CC];           // [k][o]
__device__ float g_WsrT[4 * CC * CC];         // [p*256+c][o]
__device__ float g_XS[NSTREAM * BB * MM * CC];        // conv out
__device__ float g_XSN[NSTREAM * BB * MM * CC];       // layernormed
__device__ float g_KV[NSTREAM * BB * MM * 2 * CC];    // [row][0:256]=K ch, [256:512]=V ch
__device__ float g_Q[NSTREAM * BB * NN * CC];
__device__ float g_AO[NSTREAM * BB * NN * CC];        // attention output (pre-proj)

// ---------------- prep: transpose weights ----------------
__global__ void prep_kernel(const float* __restrict__ Wq, const float* __restrict__ Wkv,
                            const float* __restrict__ Wproj, const float* __restrict__ Wsr) {
    int t = blockIdx.x * blockDim.x + threadIdx.x;   // 0 .. 262143
    if (t < 65536) {
        int k = t >> 8, o = t & 255;
        g_WqT[t] = Wq[o * 256 + k];
        g_WprojT[t] = Wproj[o * 256 + k];
    }
    if (t < 131072) {
        int k = t / 512, o = t % 512;
        g_WkvT[t] = Wkv[o * 256 + k];
    }
    if (t < 262144) {
        int o = t & 255;
        int kp = t >> 8;          // p*256 + c
        int p = kp >> 8;
        int c = kp & 255;
        g_WsrT[t] = Wsr[o * 1024 + c * 4 + p];
    }
}

// ---------------- generic fp32 GEMM: Y[r][o] = sum_k A[r][k]*Bt[k][o] (+bias) ----------------
__global__ void __launch_bounds__(256) gemm64_kernel(
    const float* __restrict__ A, int lda,
    const float* __restrict__ Bt, int ldb,
    const float* __restrict__ bias,
    float* __restrict__ Y, int ldc, int Kdim)
{
    __shared__ float As[64][16];
    __shared__ float Bs[16][64];
    const int tid = threadIdx.x;
    const int row0 = blockIdx.x * 64, col0 = blockIdx.y * 64;
    const int tx = tid & 15, ty = tid >> 4;
    const int ar = tid >> 2, ak = (tid & 3) << 2;
    const int bk = tid >> 4, bo = (tid & 15) << 2;

    float acc[4][4] = {};
    for (int kb = 0; kb < Kdim; kb += 16) {
        float4 av = *(const float4*)(A + (size_t)(row0 + ar) * lda + kb + ak);
        *(float4*)&As[ar][ak] = av;
        float4 bv = *(const float4*)(Bt + (size_t)(kb + bk) * ldb + col0 + bo);
        *(float4*)&Bs[bk][bo] = bv;
        __syncthreads();
#pragma unroll
        for (int k = 0; k < 16; k++) {
            float a0 = As[ty * 4 + 0][k], a1 = As[ty * 4 + 1][k];
            float a2 = As[ty * 4 + 2][k], a3 = As[ty * 4 + 3][k];
            float4 b = *(const float4*)&Bs[k][tx * 4];
            acc[0][0] += a0 * b.x; acc[0][1] += a0 * b.y; acc[0][2] += a0 * b.z; acc[0][3] += a0 * b.w;
            acc[1][0] += a1 * b.x; acc[1][1] += a1 * b.y; acc[1][2] += a1 * b.z; acc[1][3] += a1 * b.w;
            acc[2][0] += a2 * b.x; acc[2][1] += a2 * b.y; acc[2][2] += a2 * b.z; acc[2][3] += a2 * b.w;
            acc[3][0] += a3 * b.x; acc[3][1] += a3 * b.y; acc[3][2] += a3 * b.z; acc[3][3] += a3 * b.w;
        }
        __syncthreads();
    }
    float4 bb = make_float4(0.f, 0.f, 0.f, 0.f);
    if (bias) bb = *(const float4*)(bias + col0 + tx * 4);
#pragma unroll
    for (int i = 0; i < 4; i++) {
        int r = row0 + ty * 4 + i;
        float4 o;
        o.x = acc[i][0] + bb.x; o.y = acc[i][1] + bb.y;
        o.z = acc[i][2] + bb.z; o.w = acc[i][3] + bb.w;
        *(float4*)(Y + (size_t)r * ldc + col0 + tx * 4) = o;
    }
}

// ---------------- conv (SR=2) as GEMM with implicit im2col A ----------------
// rows: (s,b,m) m=i*32+j ; k' = p*256+c, p=di*2+dj ; A[row][k'] = x_s[b][(2i+di)*64+2j+dj][c]
__global__ void __launch_bounds__(256) conv_gemm_kernel(
    const float* __restrict__ x0, const float* __restrict__ x1,
    const float* __restrict__ bsr)
{
    __shared__ float As[64][16];
    __shared__ float Bs[16][64];
    const int tid = threadIdx.x;
    const int row0 = blockIdx.x * 64, col0 = blockIdx.y * 64;
    const int tx = tid & 15, ty = tid >> 4;
    const int ar = tid >> 2, ak = (tid & 3) << 2;
    const int bk = tid >> 4, bo = (tid & 15) << 2;

    const int row = row0 + ar;
    const int s = row >> 11;
    const int bdx = (row >> 10) & 1;
    const int m = row & 1023;
    const int ii = m >> 5, jj = m & 31;
    const float* Xp = s ? x1 : x0;

    float acc[4][4] = {};
    for (int kb = 0; kb < 1024; kb += 16) {
        int kg = kb + ak;
        int p = kg >> 8;
        int c = kg & 255;
        int n = ((ii * 2 + (p >> 1)) << 6) + jj * 2 + (p & 1);
        float4 av = *(const float4*)(Xp + ((size_t)bdx * NN + n) * CC + c);
        *(float4*)&As[ar][ak] = av;
        float4 bv = *(const float4*)(g_WsrT + (size_t)(kb + bk) * 256 + col0 + bo);
        *(float4*)&Bs[bk][bo] = bv;
        __syncthreads();
#pragma unroll
        for (int k = 0; k < 16; k++) {
            float a0 = As[ty * 4 + 0][k], a1 = As[ty * 4 + 1][k];
            float a2 = As[ty * 4 + 2][k], a3 = As[ty * 4 + 3][k];
            float4 b = *(const float4*)&Bs[k][tx * 4];
            acc[0][0] += a0 * b.x; acc[0][1] += a0 * b.y; acc[0][2] += a0 * b.z; acc[0][3] += a0 * b.w;
            acc[1][0] += a1 * b.x; acc[1][1] += a1 * b.y; acc[1][2] += a1 * b.z; acc[1][3] += a1 * b.w;
            acc[2][0] += a2 * b.x; acc[2][1] += a2 * b.y; acc[2][2] += a2 * b.z; acc[2][3] += a2 * b.w;
            acc[3][0] += a3 * b.x; acc[3][1] += a3 * b.y; acc[3][2] += a3 * b.z; acc[3][3] += a3 * b.w;
        }
        __syncthreads();
    }
    float4 bb = *(const float4*)(bsr + col0 + tx * 4);
#pragma unroll
    for (int i = 0; i < 4; i++) {
        int r = row0 + ty * 4 + i;
        float4 o;
        o.x = acc[i][0] + bb.x; o.y = acc[i][1] + bb.y;
        o.z = acc[i][2] + bb.z; o.w = acc[i][3] + bb.w;
        *(float4*)(g_XS + (size_t)r * CC + col0 + tx * 4) = o;
    }
}

// ---------------- LayerNorm over C=256 per row ----------------
__global__ void ln_kernel(const float* __restrict__ lnw0, const float* __restrict__ lnb0,
                          const float* __restrict__ lnw1, const float* __restrict__ lnb1)
{
    const int row = blockIdx.x;       // 4096 rows (s,b,m)
    const int c = threadIdx.x;        // 256
    const int s = row >> 11;
    __shared__ float red[8];
    __shared__ float stat[2];
    float v = g_XS[(size_t)row * 256 + c];
    float sum = v;
#pragma unroll
    for (int o = 16; o > 0; o >>= 1) sum += __shfl_xor_sync(0xffffffffu, sum, o);
    int w = c >> 5, l = c & 31;
    if (l == 0) red[w] = sum;
    __syncthreads();
    if (c == 0) {
        float t = 0.f;
        for (int k2 = 0; k2 < 8; k2++) t += red[k2];
        stat[0] = t * (1.f / 256.f);
    }
    __syncthreads();
    float mu = stat[0];
    float d = v - mu;
    float sq = d * d;
#pragma unroll
    for (int o = 16; o > 0; o >>= 1) sq += __shfl_xor_sync(0xffffffffu, sq, o);
    __syncthreads();
    if (l == 0) red[w] = sq;
    __syncthreads();
    if (c == 0) {
        float t = 0.f;
        for (int k2 = 0; k2 < 8; k2++) t += red[k2];
        stat[1] = rsqrtf(t * (1.f / 256.f) + 1e-5f);
    }
    __syncthreads();
    const float* wv = s ? lnw1 : lnw0;
    const float* bv = s ? lnb1 : lnb0;
    g_XSN[(size_t)row * 256 + c] = d * stat[1] * wv[c] + bv[c];
}

// ---------------- flash attention: Q-tile 128, K-block 64, d=32, M=1024 ----------------
#define QT 128
#define KBLK 64
__global__ void __launch_bounds__(256, 2) attn_kernel()
{
    extern __shared__ float sm[];
    float* Qs   = sm;                    // [128][32]
    float* Kst  = Qs + 128 * 32;         // [32][68]  (transposed, padded)
    float* Vs   = Kst + 32 * 68;         // [64][32]
    float* Ps   = Vs + 64 * 32;          // [128][64]
    float* corr = Ps + 128 * 64;         // [128]
    float* lsm  = corr + 128;            // [128]

    const int tid = threadIdx.x;
    const int sb = blockIdx.z;           // (s*2+b) 0..3
    const int h = blockIdx.y;
    const int n0 = blockIdx.x * QT;
    const float scale = 0.17677669529663687f;  // 1/sqrt(32)

    const float* Qg = g_Q + ((size_t)sb * NN + n0) * CC + h * DH;
    const float* Kg = g_KV + (size_t)sb * MM * 512 + h * DH;
    const float* Vg = Kg + 256;

    // load Q tile (scaled)
#pragma unroll
    for (int it = 0; it < 4; it++) {
        int f = tid + it * 256;
        int r = f >> 3, kq = (f & 7) << 2;
        float4 q = *(const float4*)(Qg + (size_t)r * CC + kq);
        q.x *= scale; q.y *= scale; q.z *= scale; q.w *= scale;
        *(float4*)&Qs[r * 32 + kq] = q;
    }

    const int tx = tid & 15, ty = tid >> 4;       // S-phase mapping: rows ty*8.., cols tx*4..
    const int pr = (tid >> 3) << 2;               // PV mapping: 4 rows
    const int pc = (tid & 7) << 2;                // 4 cols

    float mrow[8], lrow[8];
#pragma unroll
    for (int i = 0; i < 8; i++) { mrow[i] = -1e30f; lrow[i] = 0.f; }
    float oacc[4][4] = {};

    for (int mb = 0; mb < MM; mb += KBLK) {
        __syncthreads();   // prior PV done with Vs/Ps (and Qs visible on iter 0)
        // load K (transposed) + V
#pragma unroll
        for (int it = 0; it < 2; it++) {
            int f = tid + it * 256;
            int mk = f >> 3, kq = (f & 7) << 2;
            float4 kv4 = *(const float4*)(Kg + (size_t)(mb + mk) * 512 + kq);
            Kst[(kq + 0) * 68 + mk] = kv4.x;
            Kst[(kq + 1) * 68 + mk] = kv4.y;
            Kst[(kq + 2) * 68 + mk] = kv4.z;
            Kst[(kq + 3) * 68 + mk] = kv4.w;
            float4 vv = *(const float4*)(Vg + (size_t)(mb + mk) * 512 + kq);
            *(float4*)&Vs[mk * 32 + kq] = vv;
        }
        __syncthreads();
        // S = Q @ K^T  (8x4 per thread)
        float sacc[8][4] = {};
#pragma unroll
        for (int k = 0; k < 32; k++) {
            float4 bv = *(const float4*)&Kst[k * 68 + tx * 4];
#pragma unroll
            for (int i = 0; i < 8; i++) {
                float a = Qs[(ty * 8 + i) * 32 + k];
                sacc[i][0] += a * bv.x; sacc[i][1] += a * bv.y;
                sacc[i][2] += a * bv.z; sacc[i][3] += a * bv.w;
            }
        }
        // online softmax per row
#pragma unroll
        for (int i = 0; i < 8; i++) {
            float mx = fmaxf(fmaxf(sacc[i][0], sacc[i][1]), fmaxf(sacc[i][2], sacc[i][3]));
#pragma unroll
            for (int o = 8; o > 0; o >>= 1) mx = fmaxf(mx, __shfl_xor_sync(0xffffffffu, mx, o, 16));
            float mnew = fmaxf(mrow[i], mx);
            float p0 = __expf(sacc[i][0] - mnew);
            float p1 = __expf(sacc[i][1] - mnew);
            float p2 = __expf(sacc[i][2] - mnew);
            float p3 = __expf(sacc[i][3] - mnew);
            float ps = p0 + p1 + p2 + p3;
#pragma unroll
            for (int o = 8; o > 0; o >>= 1) ps += __shfl_xor_sync(0xffffffffu, ps, o, 16);
            float cf = __expf(mrow[i] - mnew);
            lrow[i] = lrow[i] * cf + ps;
            mrow[i] = mnew;
            int r = ty * 8 + i;
            *(float4*)&Ps[r * 64 + tx * 4] = make_float4(p0, p1, p2, p3);
            if (tx == 0) corr[r] = cf;
        }
        __syncthreads();
        // O = O*corr + P @ V
        float cf0 = corr[pr + 0], cf1 = corr[pr + 1], cf2 = corr[pr + 2], cf3 = corr[pr + 3];
#pragma unroll
        for (int j = 0; j < 4; j++) {
            oacc[0][j] *= cf0; oacc[1][j] *= cf1; oacc[2][j] *= cf2; oacc[3][j] *= cf3;
        }
#pragma unroll
        for (int k = 0; k < KBLK; k++) {
            float4 vv = *(const float4*)&Vs[k * 32 + pc];
            float p0 = Ps[(pr + 0) * 64 + k];
            float p1 = Ps[(pr + 1) * 64 + k];
            float p2 = Ps[(pr + 2) * 64 + k];
            float p3 = Ps[(pr + 3) * 64 + k];
            oacc[0][0] += p0 * vv.x; oacc[0][1] += p0 * vv.y; oacc[0][2] += p0 * vv.z; oacc[0][3] += p0 * vv.w;
            oacc[1][0] += p1 * vv.x; oacc[1][1] += p1 * vv.y; oacc[1][2] += p1 * vv.z; oacc[1][3] += p1 * vv.w;
            oacc[2][0] += p2 * vv.x; oacc[2][1] += p2 * vv.y; oacc[2][2] += p2 * vv.z; oacc[2][3] += p2 * vv.w;
            oacc[3][0] += p3 * vv.x; oacc[3][1] += p3 * vv.y; oacc[3][2] += p3 * vv.z; oacc[3][3] += p3 * vv.w;
        }
    }
    __syncthreads();
    if (tx == 0) {
#pragma unroll
        for (int i = 0; i < 8; i++) lsm[ty * 8 + i] = lrow[i];
    }
    __syncthreads();
    float* Og = g_AO + ((size_t)sb * NN + n0) * CC + h * DH;
#pragma unroll
    for (int i = 0; i < 4; i++) {
        float inv = 1.f / lsm[pr + i];
        float4 o = make_float4(oacc[i][0] * inv, oacc[i][1] * inv, oacc[i][2] * inv, oacc[i][3] * inv);
        *(float4*)(Og + (size_t)(pr + i) * CC + pc) = o;
    }
}

// ---------------- launch ----------------
extern "C" void kernel_launch(void* const* d_in, const int* in_sizes, int n_in,
                              void* d_out, int out_size)
{
    const float* x0    = (const float*)d_in[0];
    const float* x1    = (const float*)d_in[1];
    const float* Wq    = (const float*)d_in[2];
    const float* Wkv   = (const float*)d_in[3];
    const float* Wproj = (const float*)d_in[4];
    const float* bproj = (const float*)d_in[5];
    const float* Wsr   = (const float*)d_in[6];
    const float* bsr   = (const float*)d_in[7];
    const float* lnw0  = (const float*)d_in[8];
    const float* lnb0  = (const float*)d_in[9];
    const float* lnw1  = (const float*)d_in[10];
    const float* lnb1  = (const float*)d_in[11];
    float* out = (float*)d_out;

    float *p_WqT, *p_WkvT, *p_WprojT, *p_XSN, *p_KV, *p_Q, *p_AO;
    cudaGetSymbolAddress((void**)&p_WqT, g_WqT);
    cudaGetSymbolAddress((void**)&p_WkvT, g_WkvT);
    cudaGetSymbolAddress((void**)&p_WprojT, g_WprojT);
    cudaGetSymbolAddress((void**)&p_XSN, g_XSN);
    cudaGetSymbolAddress((void**)&p_KV, g_KV);
    cudaGetSymbolAddress((void**)&p_Q, g_Q);
    cudaGetSymbolAddress((void**)&p_AO, g_AO);

    const int ATTN_SMEM = (128 * 32 + 32 * 68 + 64 * 32 + 128 * 64 + 256) * 4;
    cudaFuncSetAttribute(attn_kernel, cudaFuncAttributeMaxDynamicSharedMemorySize, ATTN_SMEM);

    // 0) transpose weights
    prep_kernel<<<1024, 256>>>(Wq, Wkv, Wproj, Wsr);
    // 1) conv (im2col GEMM) + bias -> g_XS   [4096 x 256]
    conv_gemm_kernel<<<dim3(64, 4), 256>>>(x0, x1, bsr);
    // 2) layernorm -> g_XSN
    ln_kernel<<<4096, 256>>>(lnw0, lnb0, lnw1, lnb1);
    // 3) KV = XSN @ WkvT  -> g_KV  [4096 x 512]
    gemm64_kernel<<<dim3(64, 8), 256>>>(p_XSN, 256, p_WkvT, 512, nullptr, p_KV, 512, 256);
    // 4) Q = x @ WqT per stream -> g_Q [16384 x 256]
    gemm64_kernel<<<dim3(128, 4), 256>>>(x0, 256, p_WqT, 256, nullptr, p_Q, 256, 256);
    gemm64_kernel<<<dim3(128, 4), 256>>>(x1, 256, p_WqT, 256, nullptr,
                                         p_Q + (size_t)BB * NN * CC, 256, 256);
    // 5) fused flash attention -> g_AO
    attn_kernel<<<dim3(NN / QT, NH, NSTREAM * BB), 256, ATTN_SMEM>>>();
    // 6) Y = AO @ WprojT + bproj -> d_out  [16384 x 256] = (y0, y1)
    gemm64_kernel<<<dim3(256, 4), 256>>>(p_AO, 256, p_WprojT, 256, bproj, out, 256, 256);
}

// round 3
// speedup vs baseline: 1.1100x; 1.1100x over previous
#include <cuda_runtime.h>
#include <cuda_bf16.h>
#include <math.h>
#include <stdint.h>

#define NSTREAM 2
#define BB 2
#define NN 4096
#define CC 256
#define NH 8
#define DH 32
#define MM 1024

// ================= scratch (static device globals; no allocation) =================
__device__ float g_XS[NSTREAM * BB * MM * CC];          // conv out (LN input)
__device__ float g_KV[NSTREAM * BB * MM * 2 * CC];      // [row][0:256]=K, [256:512]=V
__device__ float g_Q[NSTREAM * BB * NN * CC];
// bf16 hi/lo split operands (plane0 = hi, plane1 = lo)
#define X2_PLANE   4194304     // 16384*256
#define CA_PLANE   4194304     // 4096*1024
#define AO_PLANE   4194304     // 16384*256
#define XSN_PLANE  1048576     // 4096*256
__device__ __align__(1024) __nv_bfloat16 g_x2[2 * 16384 * 256];
__device__ __align__(1024) __nv_bfloat16 g_cA[2 * 4096 * 1024];
__device__ __align__(1024) __nv_bfloat16 g_AO2[2 * 16384 * 256];
__device__ __align__(1024) __nv_bfloat16 g_XSN2[2 * 4096 * 256];
__device__ __align__(1024) __nv_bfloat16 g_Wq2[2 * 256 * 256];
__device__ __align__(1024) __nv_bfloat16 g_Wkv2[2 * 512 * 256];
__device__ __align__(1024) __nv_bfloat16 g_Wpr2[2 * 256 * 256];
__device__ __align__(1024) __nv_bfloat16 g_Wsr2[2 * 256 * 1024];

__device__ __forceinline__ void split_f(float v, __nv_bfloat16& h, __nv_bfloat16& l) {
    h = __float2bfloat16(v);
    l = __float2bfloat16(v - __bfloat162float(h));
}

__device__ __forceinline__ uint32_t smem_u32(const void* p) {
    uint32_t a;
    asm("{ .reg .u64 tmp; cvta.to.shared.u64 tmp, %1; cvt.u32.u64 %0, tmp; }" : "=r"(a) : "l"(p));
    return a;
}

__device__ __forceinline__ void ldm4(uint32_t* r, uint32_t addr) {
    asm volatile("ldmatrix.sync.aligned.m8n8.x4.shared.b16 {%0,%1,%2,%3}, [%4];"
                 : "=r"(r[0]), "=r"(r[1]), "=r"(r[2]), "=r"(r[3]) : "r"(addr));
}

__device__ __forceinline__ void mma16816(float* c, const uint32_t* a, const uint32_t* b) {
    asm volatile("mma.sync.aligned.m16n8k16.row.col.f32.bf16.bf16.f32 "
                 "{%0,%1,%2,%3}, {%4,%5,%6,%7}, {%8,%9}, {%0,%1,%2,%3};"
                 : "+f"(c[0]), "+f"(c[1]), "+f"(c[2]), "+f"(c[3])
                 : "r"(a[0]), "r"(a[1]), "r"(a[2]), "r"(a[3]), "r"(b[0]), "r"(b[1]));
}

// ================= conversion kernels =================
__global__ void cvt_weights_kernel(const float* __restrict__ Wq, const float* __restrict__ Wkv,
                                   const float* __restrict__ Wproj, const float* __restrict__ Wsr) {
    int t = blockIdx.x * blockDim.x + threadIdx.x;   // 262144 threads
    if (t < 65536) {
        split_f(Wq[t],    g_Wq2[t],  g_Wq2[65536 + t]);
        split_f(Wproj[t], g_Wpr2[t], g_Wpr2[65536 + t]);
    }
    if (t < 131072) {
        split_f(Wkv[t], g_Wkv2[t], g_Wkv2[131072 + t]);
    }
    if (t < 262144) {
        int o = t >> 10, kp = t & 1023, p = kp >> 8, c = kp & 255;
        split_f(Wsr[o * 1024 + c * 4 + p], g_Wsr2[t], g_Wsr2[262144 + t]);
    }
}

__global__ void cvt_x_kernel(const float* __restrict__ x0, const float* __restrict__ x1) {
    size_t t = blockIdx.x * blockDim.x + threadIdx.x;   // 2,097,152 threads
    size_t e = t * 2;
    const float* src = (e < 2097152) ? (x0 + e) : (x1 + (e - 2097152));
    float2 v = *(const float2*)src;
    __nv_bfloat16 h0, l0, h1, l1;
    split_f(v.x, h0, l0);
    split_f(v.y, h1, l1);
    __nv_bfloat162 hh; hh.x = h0; hh.y = h1;
    __nv_bfloat162 ll; ll.x = l0; ll.y = l1;
    *(__nv_bfloat162*)(g_x2 + e) = hh;
    *(__nv_bfloat162*)(g_x2 + X2_PLANE + e) = ll;
}

// im2col conv operand: row=(s,b,m), k'=p*256+c, A[row][k'] = x_s[b][n(m,p)][c]
__global__ void cvt_conv_kernel(const float* __restrict__ x0, const float* __restrict__ x1) {
    int t = blockIdx.x * blockDim.x + threadIdx.x;   // 2,097,152 threads
    int e = t * 2;
    int row = e >> 10, kp = e & 1023;
    int p = kp >> 8, c = kp & 255;           // c even
    int s = row >> 11, b = (row >> 10) & 1, m = row & 1023;
    int ii = m >> 5, jj = m & 31;
    int n = ((ii * 2 + (p >> 1)) << 6) + jj * 2 + (p & 1);
    const float* src = (s ? x1 : x0) + ((size_t)(b * 4096 + n)) * 256 + c;
    float2 v = *(const float2*)src;
    __nv_bfloat16 h0, l0, h1, l1;
    split_f(v.x, h0, l0);
    split_f(v.y, h1, l1);
    __nv_bfloat162 hh; hh.x = h0; hh.y = h1;
    __nv_bfloat162 ll; ll.x = l0; ll.y = l1;
    *(__nv_bfloat162*)(g_cA + e) = hh;
    *(__nv_bfloat162*)(g_cA + CA_PLANE + e) = ll;
}

// ================= HMMA bf16-split GEMM: C[M,N] = A[M,K] @ B[N,K]^T (+bias) =================
// Block 128x128, 8 warps (4m x 2n), warp tile 32x64, KC=32.
// Smem rows padded to 56 bf16 (112 B): conflict-free ldmatrix, 16B aligned.
#define SROW 56
#define HSMEM (4 * 128 * SROW * 2)

__global__ void __launch_bounds__(256) gemm_hmma(
    const __nv_bfloat16* __restrict__ A, size_t aPlane,
    const __nv_bfloat16* __restrict__ B, size_t bPlane,
    const float* __restrict__ bias,
    float* __restrict__ C, int ldc, int K)
{
    extern __shared__ __nv_bfloat16 hsm[];
    __nv_bfloat16* sAh = hsm;
    __nv_bfloat16* sAl = sAh + 128 * SROW;
    __nv_bfloat16* sBh = sAl + 128 * SROW;
    __nv_bfloat16* sBl = sBh + 128 * SROW;

    const int tid = threadIdx.x;
    const int wid = tid >> 5, lane = tid & 31;
    const int wm = wid >> 1, wn = wid & 1;
    const int row0 = blockIdx.x * 128, col0 = blockIdx.y * 128;

    // gmem->smem mapping: 64 rows per wave, 4x 16B segs per row
    const int lr = tid >> 2;
    const int lseg = (tid & 3) * 8;            // bf16 elems
    const __nv_bfloat16* Ag = A + (size_t)(row0 + lr) * K + lseg;
    const __nv_bfloat16* Bg = B + (size_t)(col0 + lr) * K + lseg;
    const uint32_t sAoff = lr * SROW + lseg;

    // ldmatrix lane addresses (bytes)
    const uint32_t aFragOff = (((lane & 15)) * SROW + ((lane >> 4) & 1) * 8) * 2 + (wm * 32) * SROW * 2;
    const uint32_t bFragOff = (((lane & 7) + ((lane >> 4) & 1) * 8) * SROW + ((lane >> 3) & 1) * 8) * 2
                              + (wn * 64) * SROW * 2;
    const uint32_t sAh32 = smem_u32(sAh), sAl32 = smem_u32(sAl);
    const uint32_t sBh32 = smem_u32(sBh), sBl32 = smem_u32(sBl);

    float acc[2][8][4] = {};

    for (int kb = 0; kb < K; kb += 32) {
#pragma unroll
        for (int h2 = 0; h2 < 128; h2 += 64) {
            size_t go = (size_t)h2 * K + kb;
            uint32_t so = sAoff + h2 * SROW;
            *(float4*)&sAh[so] = *(const float4*)(Ag + go);
            *(float4*)&sAl[so] = *(const float4*)(Ag + aPlane + go);
            *(float4*)&sBh[so] = *(const float4*)(Bg + go);
            *(float4*)&sBl[so] = *(const float4*)(Bg + bPlane + go);
        }
        __syncthreads();
#pragma unroll
        for (int kk = 0; kk < 2; kk++) {
            uint32_t ah[2][4], al[2][4];
#pragma unroll
            for (int mi = 0; mi < 2; mi++) {
                uint32_t off = aFragOff + mi * 16 * SROW * 2 + kk * 32;
                ldm4(ah[mi], sAh32 + off);
                ldm4(al[mi], sAl32 + off);
            }
#pragma unroll
            for (int ni = 0; ni < 4; ni++) {
                uint32_t off = bFragOff + ni * 16 * SROW * 2 + kk * 32;
                uint32_t bh[4], bl[4];
                ldm4(bh, sBh32 + off);
                ldm4(bl, sBl32 + off);
#pragma unroll
                for (int mi = 0; mi < 2; mi++) {
                    mma16816(acc[mi][2 * ni],     ah[mi], bh);
                    mma16816(acc[mi][2 * ni + 1], ah[mi], bh + 2);
                    mma16816(acc[mi][2 * ni],     ah[mi], bl);
                    mma16816(acc[mi][2 * ni + 1], ah[mi], bl + 2);
                    mma16816(acc[mi][2 * ni],     al[mi], bh);
                    mma16816(acc[mi][2 * ni + 1], al[mi], bh + 2);
                }
            }
        }
        __syncthreads();
    }

    // epilogue
    const int crow = row0 + wm * 32 + (lane >> 2);
    const int ccol = col0 + wn * 64 + (lane & 3) * 2;
#pragma unroll
    for (int mi = 0; mi < 2; mi++) {
#pragma unroll
        for (int j = 0; j < 8; j++) {
            int r = crow + mi * 16;
            int c0 = ccol + j * 8;
            float b0 = 0.f, b1 = 0.f;
            if (bias) { b0 = bias[c0]; b1 = bias[c0 + 1]; }
            float2 v0 = make_float2(acc[mi][j][0] + b0, acc[mi][j][1] + b1);
            float2 v1 = make_float2(acc[mi][j][2] + b0, acc[mi][j][3] + b1);
            *(float2*)(C + (size_t)r * ldc + c0) = v0;
            *(float2*)(C + (size_t)(r + 8) * ldc + c0) = v1;
        }
    }
}

// ================= LayerNorm over C=256 per row, bf16 hi/lo output =================
__global__ void ln_kernel(const float* __restrict__ lnw0, const float* __restrict__ lnb0,
                          const float* __restrict__ lnw1, const float* __restrict__ lnb1)
{
    const int row = blockIdx.x;       // 4096 rows (s,b,m)
    const int c = threadIdx.x;        // 256
    const int s = row >> 11;
    __shared__ float red[8];
    __shared__ float stat[2];
    float v = g_XS[(size_t)row * 256 + c];
    float sum = v;
#pragma unroll
    for (int o = 16; o > 0; o >>= 1) sum += __shfl_xor_sync(0xffffffffu, sum, o);
    int w = c >> 5, l = c & 31;
    if (l == 0) red[w] = sum;
    __syncthreads();
    if (c == 0) {
        float t = 0.f;
        for (int k2 = 0; k2 < 8; k2++) t += red[k2];
        stat[0] = t * (1.f / 256.f);
    }
    __syncthreads();
    float mu = stat[0];
    float d = v - mu;
    float sq = d * d;
#pragma unroll
    for (int o = 16; o > 0; o >>= 1) sq += __shfl_xor_sync(0xffffffffu, sq, o);
    __syncthreads();
    if (l == 0) red[w] = sq;
    __syncthreads();
    if (c == 0) {
        float t = 0.f;
        for (int k2 = 0; k2 < 8; k2++) t += red[k2];
        stat[1] = rsqrtf(t * (1.f / 256.f) + 1e-5f);
    }
    __syncthreads();
    const float* wv = s ? lnw1 : lnw0;
    const float* bv = s ? lnb1 : lnb0;
    float y = d * stat[1] * wv[c] + bv[c];
    __nv_bfloat16 hh, ll;
    split_f(y, hh, ll);
    g_XSN2[(size_t)row * 256 + c] = hh;
    g_XSN2[XSN_PLANE + (size_t)row * 256 + c] = ll;
}

// ================= flash attention (fp32; bf16 hi/lo output for proj GEMM) =================
#define QT 128
#define KBLK 64
__global__ void __launch_bounds__(256, 2) attn_kernel()
{
    extern __shared__ float sm[];
    float* Qs   = sm;                    // [128][32]
    float* Kst  = Qs + 128 * 32;         // [32][68]
    float* Vs   = Kst + 32 * 68;         // [64][32]
    float* Ps   = Vs + 64 * 32;          // [128][64]
    float* corr = Ps + 128 * 64;         // [128]
    float* lsm  = corr + 128;            // [128]

    const int tid = threadIdx.x;
    const int sb = blockIdx.z;
    const int h = blockIdx.y;
    const int n0 = blockIdx.x * QT;
    const float scale = 0.17677669529663687f;

    const float* Qg = g_Q + ((size_t)sb * NN + n0) * CC + h * DH;
    const float* Kg = g_KV + (size_t)sb * MM * 512 + h * DH;
    const float* Vg = Kg + 256;

#pragma unroll
    for (int it = 0; it < 4; it++) {
        int f = tid + it * 256;
        int r = f >> 3, kq = (f & 7) << 2;
        float4 q = *(const float4*)(Qg + (size_t)r * CC + kq);
        q.x *= scale; q.y *= scale; q.z *= scale; q.w *= scale;
        *(float4*)&Qs[r * 32 + kq] = q;
    }

    const int tx = tid & 15, ty = tid >> 4;
    const int pr = (tid >> 3) << 2;
    const int pc = (tid & 7) << 2;

    float mrow[8], lrow[8];
#pragma unroll
    for (int i = 0; i < 8; i++) { mrow[i] = -1e30f; lrow[i] = 0.f; }
    float oacc[4][4] = {};

    for (int mb = 0; mb < MM; mb += KBLK) {
        __syncthreads();
#pragma unroll
        for (int it = 0; it < 2; it++) {
            int f = tid + it * 256;
            int mk = f >> 3, kq = (f & 7) << 2;
            float4 kv4 = *(const float4*)(Kg + (size_t)(mb + mk) * 512 + kq);
            Kst[(kq + 0) * 68 + mk] = kv4.x;
            Kst[(kq + 1) * 68 + mk] = kv4.y;
            Kst[(kq + 2) * 68 + mk] = kv4.z;
            Kst[(kq + 3) * 68 + mk] = kv4.w;
            float4 vv = *(const float4*)(Vg + (size_t)(mb + mk) * 512 + kq);
            *(float4*)&Vs[mk * 32 + kq] = vv;
        }
        __syncthreads();
        float sacc[8][4] = {};
#pragma unroll
        for (int k = 0; k < 32; k++) {
            float4 bv = *(const float4*)&Kst[k * 68 + tx * 4];
#pragma unroll
            for (int i = 0; i < 8; i++) {
                float a = Qs[(ty * 8 + i) * 32 + k];
                sacc[i][0] += a * bv.x; sacc[i][1] += a * bv.y;
                sacc[i][2] += a * bv.z; sacc[i][3] += a * bv.w;
            }
        }
#pragma unroll
        for (int i = 0; i < 8; i++) {
            float mx = fmaxf(fmaxf(sacc[i][0], sacc[i][1]), fmaxf(sacc[i][2], sacc[i][3]));
#pragma unroll
            for (int o = 8; o > 0; o >>= 1) mx = fmaxf(mx, __shfl_xor_sync(0xffffffffu, mx, o, 16));
            float mnew = fmaxf(mrow[i], mx);
            float p0 = __expf(sacc[i][0] - mnew);
            float p1 = __expf(sacc[i][1] - mnew);
            float p2 = __expf(sacc[i][2] - mnew);
            float p3 = __expf(sacc[i][3] - mnew);
            float ps = p0 + p1 + p2 + p3;
#pragma unroll
            for (int o = 8; o > 0; o >>= 1) ps += __shfl_xor_sync(0xffffffffu, ps, o, 16);
            float cf = __expf(mrow[i] - mnew);
            lrow[i] = lrow[i] * cf + ps;
            mrow[i] = mnew;
            int r = ty * 8 + i;
            *(float4*)&Ps[r * 64 + tx * 4] = make_float4(p0, p1, p2, p3);
            if (tx == 0) corr[r] = cf;
        }
        __syncthreads();
        float cf0 = corr[pr + 0], cf1 = corr[pr + 1], cf2 = corr[pr + 2], cf3 = corr[pr + 3];
#pragma unroll
        for (int j = 0; j < 4; j++) {
            oacc[0][j] *= cf0; oacc[1][j] *= cf1; oacc[2][j] *= cf2; oacc[3][j] *= cf3;
        }
#pragma unroll
        for (int k = 0; k < KBLK; k++) {
            float4 vv = *(const float4*)&Vs[k * 32 + pc];
            float p0 = Ps[(pr + 0) * 64 + k];
            float p1 = Ps[(pr + 1) * 64 + k];
            float p2 = Ps[(pr + 2) * 64 + k];
            float p3 = Ps[(pr + 3) * 64 + k];
            oacc[0][0] += p0 * vv.x; oacc[0][1] += p0 * vv.y; oacc[0][2] += p0 * vv.z; oacc[0][3] += p0 * vv.w;
            oacc[1][0] += p1 * vv.x; oacc[1][1] += p1 * vv.y; oacc[1][2] += p1 * vv.z; oacc[1][3] += p1 * vv.w;
            oacc[2][0] += p2 * vv.x; oacc[2][1] += p2 * vv.y; oacc[2][2] += p2 * vv.z; oacc[2][3] += p2 * vv.w;
            oacc[3][0] += p3 * vv.x; oacc[3][1] += p3 * vv.y; oacc[3][2] += p3 * vv.z; oacc[3][3] += p3 * vv.w;
        }
    }
    __syncthreads();
    if (tx == 0) {
#pragma unroll
        for (int i = 0; i < 8; i++) lsm[ty * 8 + i] = lrow[i];
    }
    __syncthreads();
#pragma unroll
    for (int i = 0; i < 4; i++) {
        float inv = 1.f / lsm[pr + i];
        size_t idx = ((size_t)sb * NN + n0 + pr + i) * 256 + h * DH + pc;
#pragma unroll
        for (int j = 0; j < 4; j++) {
            float v = oacc[i][j] * inv;
            __nv_bfloat16 hh, ll;
            split_f(v, hh, ll);
            g_AO2[idx + j] = hh;
            g_AO2[AO_PLANE + idx + j] = ll;
        }
    }
}

// ================= launch =================
extern "C" void kernel_launch(void* const* d_in, const int* in_sizes, int n_in,
                              void* d_out, int out_size)
{
    const float* x0    = (const float*)d_in[0];
    const float* x1    = (const float*)d_in[1];
    const float* Wq    = (const float*)d_in[2];
    const float* Wkv   = (const float*)d_in[3];
    const float* Wproj = (const float*)d_in[4];
    const float* bproj = (const float*)d_in[5];
    const float* Wsr   = (const float*)d_in[6];
    const float* bsr   = (const float*)d_in[7];
    const float* lnw0  = (const float*)d_in[8];
    const float* lnb0  = (const float*)d_in[9];
    const float* lnw1  = (const float*)d_in[10];
    const float* lnb1  = (const float*)d_in[11];
    float* out = (float*)d_out;

    void *p_cA, *p_Wsr2, *p_XSN2, *p_Wkv2, *p_x2, *p_Wq2, *p_AO2, *p_Wpr2;
    void *p_XS, *p_KV, *p_Q;
    cudaGetSymbolAddress(&p_cA,   g_cA);
    cudaGetSymbolAddress(&p_Wsr2, g_Wsr2);
    cudaGetSymbolAddress(&p_XSN2, g_XSN2);
    cudaGetSymbolAddress(&p_Wkv2, g_Wkv2);
    cudaGetSymbolAddress(&p_x2,   g_x2);
    cudaGetSymbolAddress(&p_Wq2,  g_Wq2);
    cudaGetSymbolAddress(&p_AO2,  g_AO2);
    cudaGetSymbolAddress(&p_Wpr2, g_Wpr2);
    cudaGetSymbolAddress(&p_XS,   g_XS);
    cudaGetSymbolAddress(&p_KV,   g_KV);
    cudaGetSymbolAddress(&p_Q,    g_Q);

    const int ATTN_SMEM = (128 * 32 + 32 * 68 + 64 * 32 + 128 * 64 + 256) * 4;
    cudaFuncSetAttribute(attn_kernel, cudaFuncAttributeMaxDynamicSharedMemorySize, ATTN_SMEM);
    cudaFuncSetAttribute(gemm_hmma, cudaFuncAttributeMaxDynamicSharedMemorySize, HSMEM);

    // 0) convert inputs/weights to bf16 hi/lo
    cvt_weights_kernel<<<1024, 256>>>(Wq, Wkv, Wproj, Wsr);
    cvt_x_kernel<<<8192, 256>>>(x0, x1);
    cvt_conv_kernel<<<8192, 256>>>(x0, x1);
    // 1) conv-as-GEMM (+bsr) -> g_XS [4096 x 256] fp32
    gemm_hmma<<<dim3(32, 2), 256, HSMEM>>>(
        (const __nv_bfloat16*)p_cA, (size_t)CA_PLANE,
        (const __nv_bfloat16*)p_Wsr2, (size_t)262144, bsr, (float*)p_XS, 256, 1024);
    // 2) layernorm -> g_XSN2 (bf16 hi/lo)
    ln_kernel<<<4096, 256>>>(lnw0, lnb0, lnw1, lnb1);
    // 3) KV -> g_KV [4096 x 512] fp32
    gemm_hmma<<<dim3(32, 4), 256, HSMEM>>>(
        (const __nv_bfloat16*)p_XSN2, (size_t)XSN_PLANE,
        (const __nv_bfloat16*)p_Wkv2, (size_t)131072, nullptr, (float*)p_KV, 512, 256);
    // 4) Q -> g_Q [16384 x 256] fp32
    gemm_hmma<<<dim3(128, 2), 256, HSMEM>>>(
        (const __nv_bfloat16*)p_x2, (size_t)X2_PLANE,
        (const __nv_bfloat16*)p_Wq2, (size_t)65536, nullptr, (float*)p_Q, 256, 256);
    // 5) flash attention -> g_AO2 (bf16 hi/lo)
    attn_kernel<<<dim3(NN / QT, NH, NSTREAM * BB), 256, ATTN_SMEM>>>();
    // 6) out-proj (+bproj) -> d_out [16384 x 256] = (y0, y1)
    gemm_hmma<<<dim3(128, 2), 256, HSMEM>>>(
        (const __nv_bfloat16*)p_AO2, (size_t)AO_PLANE,
        (const __nv_bfloat16*)p_Wpr2, (size_t)65536, bproj, out, 256, 256);
}

// round 5
// speedup vs baseline: 2.8080x; 2.5296x over previous
#include <cuda_runtime.h>
#include <cuda_bf16.h>
#include <math.h>
#include <stdint.h>

#define NSTREAM 2
#define BB 2
#define NN 4096
#define CC 256
#define NH 8
#define DH 32
#define MM 1024

// ================= scratch (static device globals; no allocation) =================
__device__ float g_XS[NSTREAM * BB * MM * CC];          // conv out (LN input)
__device__ float g_KV[NSTREAM * BB * MM * 2 * CC];      // [row][0:256]=K, [256:512]=V
__device__ float g_Q[NSTREAM * BB * NN * CC];
// bf16 hi/lo split operands (plane0 = hi, plane1 = lo)
#define X2_PLANE   4194304     // 16384*256
#define CA_PLANE   4194304     // 4096*1024
#define AO_PLANE   4194304     // 16384*256
#define XSN_PLANE  1048576     // 4096*256
__device__ __align__(1024) __nv_bfloat16 g_x2[2 * 16384 * 256];
__device__ __align__(1024) __nv_bfloat16 g_cA[2 * 4096 * 1024];
__device__ __align__(1024) __nv_bfloat16 g_AO2[2 * 16384 * 256];
__device__ __align__(1024) __nv_bfloat16 g_XSN2[2 * 4096 * 256];
__device__ __align__(1024) __nv_bfloat16 g_Wq2[2 * 256 * 256];
__device__ __align__(1024) __nv_bfloat16 g_Wkv2[2 * 512 * 256];
__device__ __align__(1024) __nv_bfloat16 g_Wpr2[2 * 256 * 256];
__device__ __align__(1024) __nv_bfloat16 g_Wsr2[2 * 256 * 1024];

__device__ __forceinline__ void split_f(float v, __nv_bfloat16& h, __nv_bfloat16& l) {
    h = __float2bfloat16(v);
    l = __float2bfloat16(v - __bfloat162float(h));
}

__device__ __forceinline__ uint32_t smem_u32(const void* p) {
    uint32_t a;
    asm("{ .reg .u64 tmp; cvta.to.shared.u64 tmp, %1; cvt.u32.u64 %0, tmp; }" : "=r"(a) : "l"(p));
    return a;
}

__device__ __forceinline__ void ldm4(uint32_t* r, uint32_t addr) {
    asm volatile("ldmatrix.sync.aligned.m8n8.x4.shared.b16 {%0,%1,%2,%3}, [%4];"
                 : "=r"(r[0]), "=r"(r[1]), "=r"(r[2]), "=r"(r[3]) : "r"(addr));
}

__device__ __forceinline__ void ldm4t(uint32_t* r, uint32_t addr) {
    asm volatile("ldmatrix.sync.aligned.m8n8.x4.trans.shared.b16 {%0,%1,%2,%3}, [%4];"
                 : "=r"(r[0]), "=r"(r[1]), "=r"(r[2]), "=r"(r[3]) : "r"(addr));
}

__device__ __forceinline__ void mma16816(float* c, const uint32_t* a, const uint32_t* b) {
    asm volatile("mma.sync.aligned.m16n8k16.row.col.f32.bf16.bf16.f32 "
                 "{%0,%1,%2,%3}, {%4,%5,%6,%7}, {%8,%9}, {%0,%1,%2,%3};"
                 : "+f"(c[0]), "+f"(c[1]), "+f"(c[2]), "+f"(c[3])
                 : "r"(a[0]), "r"(a[1]), "r"(a[2]), "r"(a[3]), "r"(b[0]), "r"(b[1]));
}

__device__ __forceinline__ void cpasync16(uint32_t saddr, const void* gaddr) {
    asm volatile("cp.async.cg.shared.global [%0], [%1], 16;" :: "r"(saddr), "l"(gaddr));
}
__device__ __forceinline__ void cpcommit() { asm volatile("cp.async.commit_group;"); }
template<int N> __device__ __forceinline__ void cpwait() {
    asm volatile("cp.async.wait_group %0;" :: "n"(N));
}

// pack2: {lo=f0, hi=f1}
__device__ __forceinline__ uint32_t pack_bf2(float f0, float f1) {
    uint32_t r;
    asm("cvt.rn.bf16x2.f32 %0, %1, %2;" : "=r"(r) : "f"(f1), "f"(f0));
    return r;
}
// hi/lo split + pack for a pair
__device__ __forceinline__ void split_pack2(float f0, float f1, uint32_t& h, uint32_t& l) {
    __nv_bfloat16 h0 = __float2bfloat16(f0), h1 = __float2bfloat16(f1);
    float r0 = f0 - __bfloat162float(h0);
    float r1 = f1 - __bfloat162float(h1);
    __nv_bfloat162 hh; hh.x = h0; hh.y = h1;
    h = *(uint32_t*)&hh;
    l = pack_bf2(r0, r1);
}

// ================= conversion kernels =================
__global__ void cvt_weights_kernel(const float* __restrict__ Wq, const float* __restrict__ Wkv,
                                   const float* __restrict__ Wproj, const float* __restrict__ Wsr) {
    int t = blockIdx.x * blockDim.x + threadIdx.x;   // 262144 threads
    if (t < 65536) {
        split_f(Wq[t],    g_Wq2[t],  g_Wq2[65536 + t]);
        split_f(Wproj[t], g_Wpr2[t], g_Wpr2[65536 + t]);
    }
    if (t < 131072) {
        split_f(Wkv[t], g_Wkv2[t], g_Wkv2[131072 + t]);
    }
    if (t < 262144) {
        int o = t >> 10, kp = t & 1023, p = kp >> 8, c = kp & 255;
        split_f(Wsr[o * 1024 + c * 4 + p], g_Wsr2[t], g_Wsr2[262144 + t]);
    }
}

__global__ void cvt_x_kernel(const float* __restrict__ x0, const float* __restrict__ x1) {
    size_t t = blockIdx.x * blockDim.x + threadIdx.x;
    size_t e = t * 2;
    const float* src = (e < 2097152) ? (x0 + e) : (x1 + (e - 2097152));
    float2 v = *(const float2*)src;
    __nv_bfloat16 h0, l0, h1, l1;
    split_f(v.x, h0, l0);
    split_f(v.y, h1, l1);
    __nv_bfloat162 hh; hh.x = h0; hh.y = h1;
    __nv_bfloat162 ll; ll.x = l0; ll.y = l1;
    *(__nv_bfloat162*)(g_x2 + e) = hh;
    *(__nv_bfloat162*)(g_x2 + X2_PLANE + e) = ll;
}

__global__ void cvt_conv_kernel(const float* __restrict__ x0, const float* __restrict__ x1) {
    int t = blockIdx.x * blockDim.x + threadIdx.x;
    int e = t * 2;
    int row = e >> 10, kp = e & 1023;
    int p = kp >> 8, c = kp & 255;
    int s = row >> 11, b = (row >> 10) & 1, m = row & 1023;
    int ii = m >> 5, jj = m & 31;
    int n = ((ii * 2 + (p >> 1)) << 6) + jj * 2 + (p & 1);
    const float* src = (s ? x1 : x0) + ((size_t)(b * 4096 + n)) * 256 + c;
    float2 v = *(const float2*)src;
    __nv_bfloat16 h0, l0, h1, l1;
    split_f(v.x, h0, l0);
    split_f(v.y, h1, l1);
    __nv_bfloat162 hh; hh.x = h0; hh.y = h1;
    __nv_bfloat162 ll; ll.x = l0; ll.y = l1;
    *(__nv_bfloat162*)(g_cA + e) = hh;
    *(__nv_bfloat162*)(g_cA + CA_PLANE + e) = ll;
}

// ================= HMMA split GEMM: 64x64 tiles, 4 warps, cp.async 2-stage =================
#define GST 40                      // smem row stride (bf16)
#define GPLANE (64 * GST)           // elems per plane
#define GSTAGE (4 * GPLANE)         // Ah, Al, Bh, Bl

__global__ void __launch_bounds__(128) gemm_hmma(
    const __nv_bfloat16* __restrict__ A, size_t aPlane,
    const __nv_bfloat16* __restrict__ B, size_t bPlane,
    const float* __restrict__ bias,
    float* __restrict__ C, int ldc, int K)
{
    __shared__ __nv_bfloat16 sm[2 * GSTAGE];
    const int tid = threadIdx.x;
    const int wid = tid >> 5, lane = tid & 31;
    const int wm = (wid >> 1) * 32, wn = (wid & 1) * 32;
    const int row0 = blockIdx.x * 64, col0 = blockIdx.y * 64;
    const uint32_t sbase = smem_u32(sm);

    // cp.async mapping: per plane 64 rows x 32 cols; 2 chunks (16B) per thread
    const int srow0 = tid >> 2, srow1 = (tid + 128) >> 2;
    const int seg0 = (tid & 3) * 8, seg1 = seg0;   // (f&3) same for f and f+128
    const __nv_bfloat16* gsrc[4][2];
    gsrc[0][0] = A + (size_t)(row0 + srow0) * K + seg0;
    gsrc[0][1] = A + (size_t)(row0 + srow1) * K + seg1;
    gsrc[1][0] = gsrc[0][0] + aPlane;
    gsrc[1][1] = gsrc[0][1] + aPlane;
    gsrc[2][0] = B + (size_t)(col0 + srow0) * K + seg0;
    gsrc[2][1] = B + (size_t)(col0 + srow1) * K + seg1;
    gsrc[3][0] = gsrc[2][0] + bPlane;
    gsrc[3][1] = gsrc[2][1] + bPlane;
    uint32_t sdst[4][2];
#pragma unroll
    for (int p = 0; p < 4; p++) {
        sdst[p][0] = sbase + (p * GPLANE + srow0 * GST + seg0) * 2;
        sdst[p][1] = sbase + (p * GPLANE + srow1 * GST + seg1) * 2;
    }

    // fragment byte offsets within a stage
    const uint32_t aoff = (wm + (lane & 15)) * (GST * 2) + ((lane >> 4) & 1) * 16;
    const uint32_t boff = (wn + (lane & 7) + ((lane >> 4) & 1) * 8) * (GST * 2) + ((lane >> 3) & 1) * 16;

    const int nk = K / 32;
    // prefetch stage 0
#pragma unroll
    for (int p = 0; p < 4; p++) {
        cpasync16(sdst[p][0], gsrc[p][0]);
        cpasync16(sdst[p][1], gsrc[p][1]);
    }
    cpcommit();

    float acc[2][4][4] = {};
    for (int kt = 0; kt < nk; kt++) {
        if (kt + 1 < nk) {
            uint32_t so = ((kt + 1) & 1) * (GSTAGE * 2);
            size_t go = (size_t)(kt + 1) * 32;
#pragma unroll
            for (int p = 0; p < 4; p++) {
                cpasync16(sdst[p][0] + so, gsrc[p][0] + go);
                cpasync16(sdst[p][1] + so, gsrc[p][1] + go);
            }
            cpcommit();
            cpwait<1>();
        } else {
            cpwait<0>();
        }
        __syncthreads();
        const uint32_t st = sbase + (kt & 1) * (GSTAGE * 2) - sbase;  // stage byte offset
        const uint32_t sA_h = sbase + (kt & 1) * (GSTAGE * 2);
        const uint32_t sA_l = sA_h + GPLANE * 2;
        const uint32_t sB_h = sA_h + 2 * GPLANE * 2;
        const uint32_t sB_l = sA_h + 3 * GPLANE * 2;
        (void)st;
#pragma unroll
        for (int ks = 0; ks < 2; ks++) {
            uint32_t ah[2][4], al[2][4];
#pragma unroll
            for (int mi = 0; mi < 2; mi++) {
                uint32_t off = aoff + mi * 16 * (GST * 2) + ks * 32;
                ldm4(ah[mi], sA_h + off);
                ldm4(al[mi], sA_l + off);
            }
#pragma unroll
            for (int ng = 0; ng < 2; ng++) {
                uint32_t off = boff + ng * 16 * (GST * 2) + ks * 32;
                uint32_t bh[4], bl[4];
                ldm4(bh, sB_h + off);
                ldm4(bl, sB_l + off);
#pragma unroll
                for (int mi = 0; mi < 2; mi++) {
                    mma16816(acc[mi][ng * 2],     ah[mi], bh);
                    mma16816(acc[mi][ng * 2 + 1], ah[mi], bh + 2);
                    mma16816(acc[mi][ng * 2],     ah[mi], bl);
                    mma16816(acc[mi][ng * 2 + 1], ah[mi], bl + 2);
                    mma16816(acc[mi][ng * 2],     al[mi], bh);
                    mma16816(acc[mi][ng * 2 + 1], al[mi], bh + 2);
                }
            }
        }
        __syncthreads();
    }

    // epilogue
#pragma unroll
    for (int mi = 0; mi < 2; mi++) {
        int r0 = row0 + wm + mi * 16 + (lane >> 2);
#pragma unroll
        for (int j = 0; j < 4; j++) {
            int c0 = col0 + wn + j * 8 + (lane & 3) * 2;
            float b0 = 0.f, b1 = 0.f;
            if (bias) { b0 = bias[c0]; b1 = bias[c0 + 1]; }
            *(float2*)(C + (size_t)r0 * ldc + c0) =
                make_float2(acc[mi][j][0] + b0, acc[mi][j][1] + b1);
            *(float2*)(C + (size_t)(r0 + 8) * ldc + c0) =
                make_float2(acc[mi][j][2] + b0, acc[mi][j][3] + b1);
        }
    }
}

// ================= LayerNorm over C=256 per row, bf16 hi/lo output =================
__global__ void ln_kernel(const float* __restrict__ lnw0, const float* __restrict__ lnb0,
                          const float* __restrict__ lnw1, const float* __restrict__ lnb1)
{
    const int row = blockIdx.x;
    const int c = threadIdx.x;
    const int s = row >> 11;
    __shared__ float red[8];
    __shared__ float stat[2];
    float v = g_XS[(size_t)row * 256 + c];
    float sum = v;
#pragma unroll
    for (int o = 16; o > 0; o >>= 1) sum += __shfl_xor_sync(0xffffffffu, sum, o);
    int w = c >> 5, l = c & 31;
    if (l == 0) red[w] = sum;
    __syncthreads();
    if (c == 0) {
        float t = 0.f;
        for (int k2 = 0; k2 < 8; k2++) t += red[k2];
        stat[0] = t * (1.f / 256.f);
    }
    __syncthreads();
    float mu = stat[0];
    float d = v - mu;
    float sq = d * d;
#pragma unroll
    for (int o = 16; o > 0; o >>= 1) sq += __shfl_xor_sync(0xffffffffu, sq, o);
    __syncthreads();
    if (l == 0) red[w] = sq;
    __syncthreads();
    if (c == 0) {
        float t = 0.f;
        for (int k2 = 0; k2 < 8; k2++) t += red[k2];
        stat[1] = rsqrtf(t * (1.f / 256.f) + 1e-5f);
    }
    __syncthreads();
    const float* wv = s ? lnw1 : lnw0;
    const float* bv = s ? lnb1 : lnb0;
    float y = d * stat[1] * wv[c] + bv[c];
    __nv_bfloat16 hh, ll;
    split_f(y, hh, ll);
    g_XSN2[(size_t)row * 256 + c] = hh;
    g_XSN2[XSN_PLANE + (size_t)row * 256 + c] = ll;
}

// ================= HMMA flash attention =================
// CTA: 128 q-rows, one (sb, h). 8 warps, each owns 16 q-rows. Loop 16 m-blocks of 64.
// S = Qbf16 @ Kbf16^T (fp32 acc). PV = 3-pass split (Ph*Vh + Ph*Vl + Pl*Vh).
#define AST 40      // smem row stride bf16
__global__ void __launch_bounds__(256) attn_hmma()
{
    __shared__ __nv_bfloat16 Qs[128 * AST];
    __shared__ __nv_bfloat16 Ks[64 * AST];
    __shared__ __nv_bfloat16 Vh[64 * AST];
    __shared__ __nv_bfloat16 Vl[64 * AST];

    const int tid = threadIdx.x;
    const int w = tid >> 5, lane = tid & 31;
    const int sb = blockIdx.z;
    const int h = blockIdx.y;
    const int n0 = blockIdx.x * 128;
    const float scale = 0.17677669529663687f;

    const float* Qg = g_Q + ((size_t)sb * NN + n0) * CC + h * DH;
    const float* Kg = g_KV + (size_t)sb * MM * 512 + h * DH;
    const float* Vg = Kg + 256;

    // ---- load Q tile (scaled, bf16) ----
#pragma unroll
    for (int it = 0; it < 2; it++) {
        int f = tid + it * 256;
        int r = f >> 2, d8 = (f & 3) * 8;
        float4 a = *(const float4*)(Qg + (size_t)r * CC + d8);
        float4 b = *(const float4*)(Qg + (size_t)r * CC + d8 + 4);
        uint32_t pk[4];
        pk[0] = pack_bf2(a.x * scale, a.y * scale);
        pk[1] = pack_bf2(a.z * scale, a.w * scale);
        pk[2] = pack_bf2(b.x * scale, b.y * scale);
        pk[3] = pack_bf2(b.z * scale, b.w * scale);
        *(uint4*)&Qs[r * AST + d8] = *(uint4*)pk;
    }
    __syncthreads();

    // ---- Q fragments (held in regs for whole kernel) ----
    const uint32_t qsb = smem_u32(Qs);
    const uint32_t ksb = smem_u32(Ks);
    const uint32_t vhb = smem_u32(Vh);
    const uint32_t vlb = smem_u32(Vl);
    uint32_t qf[2][4];
#pragma unroll
    for (int ks = 0; ks < 2; ks++) {
        uint32_t off = (w * 16 + (lane & 15)) * (AST * 2) + ks * 32 + ((lane >> 4) & 1) * 16;
        ldm4(qf[ks], qsb + off);
    }

    float m0 = -1e30f, m1 = -1e30f, l0 = 0.f, l1 = 0.f;
    float oacc[4][4] = {};

    for (int mb = 0; mb < 16; mb++) {
        __syncthreads();
        // ---- load K (bf16), V (split hi/lo) ----
        {
            int r = tid >> 2, d8 = (tid & 3) * 8;
            const float* kp = Kg + (size_t)(mb * 64 + r) * 512 + d8;
            float4 a = *(const float4*)kp;
            float4 b = *(const float4*)(kp + 4);
            uint32_t pk[4];
            pk[0] = pack_bf2(a.x, a.y); pk[1] = pack_bf2(a.z, a.w);
            pk[2] = pack_bf2(b.x, b.y); pk[3] = pack_bf2(b.z, b.w);
            *(uint4*)&Ks[r * AST + d8] = *(uint4*)pk;

            const float* vp = Vg + (size_t)(mb * 64 + r) * 512 + d8;
            float4 va = *(const float4*)vp;
            float4 vb = *(const float4*)(vp + 4);
            uint32_t ph[4], pl[4];
            split_pack2(va.x, va.y, ph[0], pl[0]);
            split_pack2(va.z, va.w, ph[1], pl[1]);
            split_pack2(vb.x, vb.y, ph[2], pl[2]);
            split_pack2(vb.z, vb.w, ph[3], pl[3]);
            *(uint4*)&Vh[r * AST + d8] = *(uint4*)ph;
            *(uint4*)&Vl[r * AST + d8] = *(uint4*)pl;
        }
        __syncthreads();

        // ---- S = Q @ K^T : 8 n-tiles (64 m-cols) ----
        float sacc[8][4] = {};
#pragma unroll
        for (int ks = 0; ks < 2; ks++) {
#pragma unroll
            for (int g = 0; g < 4; g++) {
                uint32_t off = (g * 16 + (lane & 7) + ((lane >> 4) & 1) * 8) * (AST * 2)
                               + ks * 32 + ((lane >> 3) & 1) * 16;
                uint32_t bk[4];
                ldm4(bk, ksb + off);
                mma16816(sacc[g * 2],     qf[ks], bk);
                mma16816(sacc[g * 2 + 1], qf[ks], bk + 2);
            }
        }

        // ---- online softmax (rows r0=lane>>2, r1=r0+8; quad-lane reduce) ----
        float mx0 = -1e30f, mx1 = -1e30f;
#pragma unroll
        for (int j = 0; j < 8; j++) {
            mx0 = fmaxf(mx0, fmaxf(sacc[j][0], sacc[j][1]));
            mx1 = fmaxf(mx1, fmaxf(sacc[j][2], sacc[j][3]));
        }
        mx0 = fmaxf(mx0, __shfl_xor_sync(0xffffffffu, mx0, 1));
        mx0 = fmaxf(mx0, __shfl_xor_sync(0xffffffffu, mx0, 2));
        mx1 = fmaxf(mx1, __shfl_xor_sync(0xffffffffu, mx1, 1));
        mx1 = fmaxf(mx1, __shfl_xor_sync(0xffffffffu, mx1, 2));
        float mn0 = fmaxf(m0, mx0), mn1 = fmaxf(m1, mx1);
        float cf0 = __expf(m0 - mn0), cf1 = __expf(m1 - mn1);
        m0 = mn0; m1 = mn1;
        float s0 = 0.f, s1 = 0.f;
#pragma unroll
        for (int j = 0; j < 8; j++) {
            sacc[j][0] = __expf(sacc[j][0] - mn0);
            sacc[j][1] = __expf(sacc[j][1] - mn0);
            sacc[j][2] = __expf(sacc[j][2] - mn1);
            sacc[j][3] = __expf(sacc[j][3] - mn1);
            s0 += sacc[j][0] + sacc[j][1];
            s1 += sacc[j][2] + sacc[j][3];
        }
        s0 += __shfl_xor_sync(0xffffffffu, s0, 1);
        s0 += __shfl_xor_sync(0xffffffffu, s0, 2);
        s1 += __shfl_xor_sync(0xffffffffu, s1, 1);
        s1 += __shfl_xor_sync(0xffffffffu, s1, 2);
        l0 = l0 * cf0 + s0;
        l1 = l1 * cf1 + s1;
#pragma unroll
        for (int d = 0; d < 4; d++) {
            oacc[d][0] *= cf0; oacc[d][1] *= cf0;
            oacc[d][2] *= cf1; oacc[d][3] *= cf1;
        }

        // ---- O += P @ V (3-pass split) ----
#pragma unroll
        for (int t = 0; t < 4; t++) {
            uint32_t ph[4], pl[4];
            split_pack2(sacc[2 * t][0],     sacc[2 * t][1],     ph[0], pl[0]);
            split_pack2(sacc[2 * t][2],     sacc[2 * t][3],     ph[1], pl[1]);
            split_pack2(sacc[2 * t + 1][0], sacc[2 * t + 1][1], ph[2], pl[2]);
            split_pack2(sacc[2 * t + 1][2], sacc[2 * t + 1][3], ph[3], pl[3]);
            uint32_t r_base = (t * 16 + (lane & 7) + ((lane >> 3) & 1) * 8) * (AST * 2)
                              + ((lane >> 4) & 1) * 16;
            uint32_t vh0[4], vh1[4], vl0[4], vl1[4];
            ldm4t(vh0, vhb + r_base);
            ldm4t(vh1, vhb + r_base + 32);
            ldm4t(vl0, vlb + r_base);
            ldm4t(vl1, vlb + r_base + 32);
            mma16816(oacc[0], ph, vh0); mma16816(oacc[1], ph, vh0 + 2);
            mma16816(oacc[2], ph, vh1); mma16816(oacc[3], ph, vh1 + 2);
            mma16816(oacc[0], ph, vl0); mma16816(oacc[1], ph, vl0 + 2);
            mma16816(oacc[2], ph, vl1); mma16816(oacc[3], ph, vl1 + 2);
            mma16816(oacc[0], pl, vh0); mma16816(oacc[1], pl, vh0 + 2);
            mma16816(oacc[2], pl, vh1); mma16816(oacc[3], pl, vh1 + 2);
        }
    }

    // ---- final normalize + hi/lo split store ----
    float inv0 = 1.f / l0, inv1 = 1.f / l1;
    size_t base0 = ((size_t)sb * NN + n0 + w * 16 + (lane >> 2)) * 256 + h * DH;
    size_t base1 = base0 + 8 * 256;
#pragma unroll
    for (int jt = 0; jt < 4; jt++) {
        int d0 = jt * 8 + (lane & 3) * 2;
        uint32_t h0p, l0p, h1p, l1p;
        split_pack2(oacc[jt][0] * inv0, oacc[jt][1] * inv0, h0p, l0p);
        split_pack2(oacc[jt][2] * inv1, oacc[jt][3] * inv1, h1p, l1p);
        *(uint32_t*)(g_AO2 + base0 + d0) = h0p;
        *(uint32_t*)(g_AO2 + AO_PLANE + base0 + d0) = l0p;
        *(uint32_t*)(g_AO2 + base1 + d0) = h1p;
        *(uint32_t*)(g_AO2 + AO_PLANE + base1 + d0) = l1p;
    }
}

// ================= launch =================
extern "C" void kernel_launch(void* const* d_in, const int* in_sizes, int n_in,
                              void* d_out, int out_size)
{
    const float* x0    = (const float*)d_in[0];
    const float* x1    = (const float*)d_in[1];
    const float* Wq    = (const float*)d_in[2];
    const float* Wkv   = (const float*)d_in[3];
    const float* Wproj = (const float*)d_in[4];
    const float* bproj = (const float*)d_in[5];
    const float* Wsr   = (const float*)d_in[6];
    const float* bsr   = (const float*)d_in[7];
    const float* lnw0  = (const float*)d_in[8];
    const float* lnb0  = (const float*)d_in[9];
    const float* lnw1  = (const float*)d_in[10];
    const float* lnb1  = (const float*)d_in[11];
    float* out = (float*)d_out;

    void *p_cA, *p_Wsr2, *p_XSN2, *p_Wkv2, *p_x2, *p_Wq2, *p_AO2, *p_Wpr2;
    void *p_XS, *p_KV, *p_Q;
    cudaGetSymbolAddress(&p_cA,   g_cA);
    cudaGetSymbolAddress(&p_Wsr2, g_Wsr2);
    cudaGetSymbolAddress(&p_XSN2, g_XSN2);
    cudaGetSymbolAddress(&p_Wkv2, g_Wkv2);
    cudaGetSymbolAddress(&p_x2,   g_x2);
    cudaGetSymbolAddress(&p_Wq2,  g_Wq2);
    cudaGetSymbolAddress(&p_AO2,  g_AO2);
    cudaGetSymbolAddress(&p_Wpr2, g_Wpr2);
    cudaGetSymbolAddress(&p_XS,   g_XS);
    cudaGetSymbolAddress(&p_KV,   g_KV);
    cudaGetSymbolAddress(&p_Q,    g_Q);

    // 0) convert inputs/weights to bf16 hi/lo
    cvt_weights_kernel<<<1024, 256>>>(Wq, Wkv, Wproj, Wsr);
    cvt_x_kernel<<<8192, 256>>>(x0, x1);
    cvt_conv_kernel<<<8192, 256>>>(x0, x1);
    // 1) conv-as-GEMM (+bsr) -> g_XS [4096 x 256] fp32
    gemm_hmma<<<dim3(64, 4), 128>>>(
        (const __nv_bfloat16*)p_cA, (size_t)CA_PLANE,
        (const __nv_bfloat16*)p_Wsr2, (size_t)262144, bsr, (float*)p_XS, 256, 1024);
    // 2) layernorm -> g_XSN2 (bf16 hi/lo)
    ln_kernel<<<4096, 256>>>(lnw0, lnb0, lnw1, lnb1);
    // 3) KV -> g_KV [4096 x 512] fp32
    gemm_hmma<<<dim3(64, 8), 128>>>(
        (const __nv_bfloat16*)p_XSN2, (size_t)XSN_PLANE,
        (const __nv_bfloat16*)p_Wkv2, (size_t)131072, nullptr, (float*)p_KV, 512, 256);
    // 4) Q -> g_Q [16384 x 256] fp32
    gemm_hmma<<<dim3(256, 4), 128>>>(
        (const __nv_bfloat16*)p_x2, (size_t)X2_PLANE,
        (const __nv_bfloat16*)p_Wq2, (size_t)65536, nullptr, (float*)p_Q, 256, 256);
    // 5) HMMA flash attention -> g_AO2 (bf16 hi/lo)
    attn_hmma<<<dim3(NN / 128, NH, NSTREAM * BB), 256>>>();
    // 6) out-proj (+bproj) -> d_out [16384 x 256] = (y0, y1)
    gemm_hmma<<<dim3(256, 4), 128>>>(
        (const __nv_bfloat16*)p_AO2, (size_t)AO_PLANE,
        (const __nv_bfloat16*)p_Wpr2, (size_t)65536, bproj, out, 256, 256);
}

// round 6
// speedup vs baseline: 3.0255x; 1.0775x over previous
#include <cuda_runtime.h>
#include <cuda_bf16.h>
#include <math.h>
#include <stdint.h>

#define NSTREAM 2
#define BB 2
#define NN 4096
#define CC 256
#define NH 8
#define DH 32
#define MM 1024

// ================= scratch (static device globals; no allocation) =================
__device__ float g_XS[NSTREAM * BB * MM * CC];          // conv out (LN input)
#define X2_PLANE   4194304     // 16384*256
#define AO_PLANE   4194304     // 16384*256
#define XSN_PLANE  1048576     // 4096*256
__device__ __align__(1024) __nv_bfloat16 g_x2[2 * 16384 * 256];    // x hi/lo
__device__ __align__(1024) __nv_bfloat16 g_AO2[2 * 16384 * 256];   // attn out hi/lo
__device__ __align__(1024) __nv_bfloat16 g_XSN2[2 * 4096 * 256];   // LN out hi/lo
__device__ __align__(1024) __nv_bfloat16 g_Wq2[2 * 256 * 256];
__device__ __align__(1024) __nv_bfloat16 g_Wkv2[2 * 512 * 256];
__device__ __align__(1024) __nv_bfloat16 g_Wpr2[2 * 256 * 256];
__device__ __align__(1024) __nv_bfloat16 g_Wsr2[2 * 256 * 1024];
// bf16 attention operands (produced by GEMM epilogues)
__device__ __align__(1024) __nv_bfloat16 g_Qb[16384 * 256];        // pre-scaled Q
__device__ __align__(1024) __nv_bfloat16 g_Kb[4 * 1024 * 256];
__device__ __align__(1024) __nv_bfloat16 g_Vh[4 * 1024 * 256];
__device__ __align__(1024) __nv_bfloat16 g_Vl[4 * 1024 * 256];

__device__ __forceinline__ void split_f(float v, __nv_bfloat16& h, __nv_bfloat16& l) {
    h = __float2bfloat16(v);
    l = __float2bfloat16(v - __bfloat162float(h));
}

__device__ __forceinline__ uint32_t smem_u32(const void* p) {
    uint32_t a;
    asm("{ .reg .u64 tmp; cvta.to.shared.u64 tmp, %1; cvt.u32.u64 %0, tmp; }" : "=r"(a) : "l"(p));
    return a;
}

__device__ __forceinline__ void ldm4(uint32_t* r, uint32_t addr) {
    asm volatile("ldmatrix.sync.aligned.m8n8.x4.shared.b16 {%0,%1,%2,%3}, [%4];"
                 : "=r"(r[0]), "=r"(r[1]), "=r"(r[2]), "=r"(r[3]) : "r"(addr));
}

__device__ __forceinline__ void ldm4t(uint32_t* r, uint32_t addr) {
    asm volatile("ldmatrix.sync.aligned.m8n8.x4.trans.shared.b16 {%0,%1,%2,%3}, [%4];"
                 : "=r"(r[0]), "=r"(r[1]), "=r"(r[2]), "=r"(r[3]) : "r"(addr));
}

__device__ __forceinline__ void mma16816(float* c, const uint32_t* a, const uint32_t* b) {
    asm volatile("mma.sync.aligned.m16n8k16.row.col.f32.bf16.bf16.f32 "
                 "{%0,%1,%2,%3}, {%4,%5,%6,%7}, {%8,%9}, {%0,%1,%2,%3};"
                 : "+f"(c[0]), "+f"(c[1]), "+f"(c[2]), "+f"(c[3])
                 : "r"(a[0]), "r"(a[1]), "r"(a[2]), "r"(a[3]), "r"(b[0]), "r"(b[1]));
}

__device__ __forceinline__ void cpasync16(uint32_t saddr, const void* gaddr) {
    asm volatile("cp.async.cg.shared.global [%0], [%1], 16;" :: "r"(saddr), "l"(gaddr));
}
__device__ __forceinline__ void cpcommit() { asm volatile("cp.async.commit_group;"); }
template<int N> __device__ __forceinline__ void cpwait() {
    asm volatile("cp.async.wait_group %0;" :: "n"(N));
}

// pack2: {lo=f0, hi=f1} round-to-nearest
__device__ __forceinline__ uint32_t pack_bf2(float f0, float f1) {
    uint32_t r;
    asm("cvt.rn.bf16x2.f32 %0, %1, %2;" : "=r"(r) : "f"(f1), "f"(f0));
    return r;
}
// Dekker truncation split for a pair: hi = truncate-to-bf16 (exact residual), lo = RN(resid)
__device__ __forceinline__ void fsplit2(float f0, float f1, uint32_t& h, uint32_t& l) {
    uint32_t u0 = __float_as_uint(f0) & 0xFFFF0000u;
    uint32_t u1 = __float_as_uint(f1) & 0xFFFF0000u;
    h = __byte_perm(u0, u1, 0x7632);
    l = pack_bf2(f0 - __uint_as_float(u0), f1 - __uint_as_float(u1));
}

// ================= conversion kernels =================
__global__ void cvt_weights_kernel(const float* __restrict__ Wq, const float* __restrict__ Wkv,
                                   const float* __restrict__ Wproj, const float* __restrict__ Wsr) {
    int t = blockIdx.x * blockDim.x + threadIdx.x;
    if (t < 65536) {
        split_f(Wq[t],    g_Wq2[t],  g_Wq2[65536 + t]);
        split_f(Wproj[t], g_Wpr2[t], g_Wpr2[65536 + t]);
    }
    if (t < 131072) {
        split_f(Wkv[t], g_Wkv2[t], g_Wkv2[131072 + t]);
    }
    if (t < 262144) {
        int o = t >> 10, kp = t & 1023, p = kp >> 8, c = kp & 255;
        split_f(Wsr[o * 1024 + c * 4 + p], g_Wsr2[t], g_Wsr2[262144 + t]);
    }
}

__global__ void cvt_x_kernel(const float* __restrict__ x0, const float* __restrict__ x1) {
    size_t t = blockIdx.x * blockDim.x + threadIdx.x;
    size_t e = t * 2;
    const float* src = (e < 2097152) ? (x0 + e) : (x1 + (e - 2097152));
    float2 v = *(const float2*)src;
    __nv_bfloat16 h0, l0, h1, l1;
    split_f(v.x, h0, l0);
    split_f(v.y, h1, l1);
    __nv_bfloat162 hh; hh.x = h0; hh.y = h1;
    __nv_bfloat162 ll; ll.x = l0; ll.y = l1;
    *(__nv_bfloat162*)(g_x2 + e) = hh;
    *(__nv_bfloat162*)(g_x2 + X2_PLANE + e) = ll;
}

// ================= HMMA split GEMM (64x64 tiles, 4 warps, 2-stage cp.async) =================
// MODE 0: fp32 out (+bias). MODE 1: bf16 out (scaled). MODE 2: KV split (K bf16, V hi/lo).
// CONV: A gathered from g_x2 via implicit im2col row remap (K=1024).
#define GST 40
#define GPLANE (64 * GST)
#define GSTAGE (4 * GPLANE)

template<int MODE, bool CONV>
__global__ void __launch_bounds__(128) gemmT(
    const __nv_bfloat16* __restrict__ A, size_t aPlane,
    const __nv_bfloat16* __restrict__ B, size_t bPlane,
    const float* __restrict__ bias,
    float* __restrict__ Cf,
    __nv_bfloat16* __restrict__ Cb0,
    __nv_bfloat16* __restrict__ Cb1,
    __nv_bfloat16* __restrict__ Cb2,
    float oscale, int ldc, int K)
{
    __shared__ __nv_bfloat16 sm[2 * GSTAGE];
    const int tid = threadIdx.x;
    const int wid = tid >> 5, lane = tid & 31;
    const int wm = (wid >> 1) * 32, wn = (wid & 1) * 32;
    const int row0 = blockIdx.x * 64, col0 = blockIdx.y * 64;
    const uint32_t sbase = smem_u32(sm);

    const int srow0 = tid >> 2, srow1 = srow0 + 32;
    const int seg = (tid & 3) * 8;

    // A source addressing
    size_t rowA0 = 0, rowA1 = 0, eA0 = 0, eA1 = 0;
    if (CONV) {
        int gr0 = row0 + srow0, gr1 = row0 + srow1;
        int sbb0 = gr0 >> 10, m0 = gr0 & 1023;
        int sbb1 = gr1 >> 10, m1 = gr1 & 1023;
        eA0 = (size_t)sbb0 * 1048576 + (size_t)(m0 >> 5) * 32768 + (size_t)(m0 & 31) * 512 + seg;
        eA1 = (size_t)sbb1 * 1048576 + (size_t)(m1 >> 5) * 32768 + (size_t)(m1 & 31) * 512 + seg;
    } else {
        rowA0 = (size_t)(row0 + srow0) * K + seg;
        rowA1 = (size_t)(row0 + srow1) * K + seg;
    }
    const size_t rowB0 = (size_t)(col0 + srow0) * K + seg;
    const size_t rowB1 = (size_t)(col0 + srow1) * K + seg;

    uint32_t sd[4][2];
#pragma unroll
    for (int p = 0; p < 4; p++) {
        sd[p][0] = sbase + (p * GPLANE + srow0 * GST + seg) * 2;
        sd[p][1] = sbase + (p * GPLANE + srow1 * GST + seg) * 2;
    }

    auto prefetch = [&](int kt, int stg) {
        uint32_t so = stg * (GSTAGE * 2);
        size_t oA0, oA1;
        if (CONV) {
            int p = kt >> 3;
            size_t off = (size_t)(p >> 1) * 16384 + (size_t)(p & 1) * 256 + (kt & 7) * 32;
            oA0 = eA0 + off; oA1 = eA1 + off;
        } else {
            oA0 = rowA0 + (size_t)kt * 32; oA1 = rowA1 + (size_t)kt * 32;
        }
        size_t oB = (size_t)kt * 32;
        cpasync16(sd[0][0] + so, A + oA0);
        cpasync16(sd[0][1] + so, A + oA1);
        cpasync16(sd[1][0] + so, A + aPlane + oA0);
        cpasync16(sd[1][1] + so, A + aPlane + oA1);
        cpasync16(sd[2][0] + so, B + rowB0 + oB);
        cpasync16(sd[2][1] + so, B + rowB1 + oB);
        cpasync16(sd[3][0] + so, B + bPlane + rowB0 + oB);
        cpasync16(sd[3][1] + so, B + bPlane + rowB1 + oB);
        cpcommit();
    };

    const uint32_t aoff = (wm + (lane & 15)) * (GST * 2) + ((lane >> 4) & 1) * 16;
    const uint32_t boff = (wn + (lane & 7) + ((lane >> 4) & 1) * 8) * (GST * 2) + ((lane >> 3) & 1) * 16;

    const int nk = K / 32;
    prefetch(0, 0);

    float acc[2][4][4] = {};
    for (int kt = 0; kt < nk; kt++) {
        if (kt + 1 < nk) { prefetch(kt + 1, (kt + 1) & 1); cpwait<1>(); }
        else cpwait<0>();
        __syncthreads();
        const uint32_t sA_h = sbase + (kt & 1) * (GSTAGE * 2);
        const uint32_t sA_l = sA_h + GPLANE * 2;
        const uint32_t sB_h = sA_h + 2 * GPLANE * 2;
        const uint32_t sB_l = sA_h + 3 * GPLANE * 2;
#pragma unroll
        for (int ks = 0; ks < 2; ks++) {
            uint32_t ah[2][4], al[2][4];
#pragma unroll
            for (int mi = 0; mi < 2; mi++) {
                uint32_t off = aoff + mi * 16 * (GST * 2) + ks * 32;
                ldm4(ah[mi], sA_h + off);
                ldm4(al[mi], sA_l + off);
            }
#pragma unroll
            for (int ng = 0; ng < 2; ng++) {
                uint32_t off = boff + ng * 16 * (GST * 2) + ks * 32;
                uint32_t bh[4], bl[4];
                ldm4(bh, sB_h + off);
                ldm4(bl, sB_l + off);
#pragma unroll
                for (int mi = 0; mi < 2; mi++) {
                    mma16816(acc[mi][ng * 2],     ah[mi], bh);
                    mma16816(acc[mi][ng * 2 + 1], ah[mi], bh + 2);
                    mma16816(acc[mi][ng * 2],     ah[mi], bl);
                    mma16816(acc[mi][ng * 2 + 1], ah[mi], bl + 2);
                    mma16816(acc[mi][ng * 2],     al[mi], bh);
                    mma16816(acc[mi][ng * 2 + 1], al[mi], bh + 2);
                }
            }
        }
        __syncthreads();
    }

    // epilogue
#pragma unroll
    for (int mi = 0; mi < 2; mi++) {
        int r0 = row0 + wm + mi * 16 + (lane >> 2);
#pragma unroll
        for (int j = 0; j < 4; j++) {
            int c0 = col0 + wn + j * 8 + (lane & 3) * 2;
            float a0 = acc[mi][j][0], a1 = acc[mi][j][1];
            float a2 = acc[mi][j][2], a3 = acc[mi][j][3];
            if (MODE == 0) {
                float b0 = 0.f, b1 = 0.f;
                if (bias) { b0 = bias[c0]; b1 = bias[c0 + 1]; }
                *(float2*)(Cf + (size_t)r0 * ldc + c0) = make_float2(a0 + b0, a1 + b1);
                *(float2*)(Cf + (size_t)(r0 + 8) * ldc + c0) = make_float2(a2 + b0, a3 + b1);
            } else if (MODE == 1) {
                *(uint32_t*)(Cb0 + (size_t)r0 * ldc + c0) = pack_bf2(a0 * oscale, a1 * oscale);
                *(uint32_t*)(Cb0 + (size_t)(r0 + 8) * ldc + c0) = pack_bf2(a2 * oscale, a3 * oscale);
            } else {
                if (col0 < 256) {   // K part
                    *(uint32_t*)(Cb0 + (size_t)r0 * 256 + c0) = pack_bf2(a0, a1);
                    *(uint32_t*)(Cb0 + (size_t)(r0 + 8) * 256 + c0) = pack_bf2(a2, a3);
                } else {            // V part: hi/lo split
                    int cv = c0 - 256;
                    uint32_t h, l;
                    fsplit2(a0, a1, h, l);
                    *(uint32_t*)(Cb1 + (size_t)r0 * 256 + cv) = h;
                    *(uint32_t*)(Cb2 + (size_t)r0 * 256 + cv) = l;
                    fsplit2(a2, a3, h, l);
                    *(uint32_t*)(Cb1 + (size_t)(r0 + 8) * 256 + cv) = h;
                    *(uint32_t*)(Cb2 + (size_t)(r0 + 8) * 256 + cv) = l;
                }
            }
        }
    }
}

// ================= LayerNorm over C=256 per row, bf16 hi/lo output =================
__global__ void ln_kernel(const float* __restrict__ lnw0, const float* __restrict__ lnb0,
                          const float* __restrict__ lnw1, const float* __restrict__ lnb1)
{
    const int row = blockIdx.x;
    const int c = threadIdx.x;
    const int s = row >> 11;
    __shared__ float red[8];
    __shared__ float stat[2];
    float v = g_XS[(size_t)row * 256 + c];
    float sum = v;
#pragma unroll
    for (int o = 16; o > 0; o >>= 1) sum += __shfl_xor_sync(0xffffffffu, sum, o);
    int w = c >> 5, l = c & 31;
    if (l == 0) red[w] = sum;
    __syncthreads();
    if (c == 0) {
        float t = 0.f;
        for (int k2 = 0; k2 < 8; k2++) t += red[k2];
        stat[0] = t * (1.f / 256.f);
    }
    __syncthreads();
    float mu = stat[0];
    float d = v - mu;
    float sq = d * d;
#pragma unroll
    for (int o = 16; o > 0; o >>= 1) sq += __shfl_xor_sync(0xffffffffu, sq, o);
    __syncthreads();
    if (l == 0) red[w] = sq;
    __syncthreads();
    if (c == 0) {
        float t = 0.f;
        for (int k2 = 0; k2 < 8; k2++) t += red[k2];
        stat[1] = rsqrtf(t * (1.f / 256.f) + 1e-5f);
    }
    __syncthreads();
    const float* wv = s ? lnw1 : lnw0;
    const float* bv = s ? lnb1 : lnb0;
    float y = d * stat[1] * wv[c] + bv[c];
    __nv_bfloat16 hh, ll;
    split_f(y, hh, ll);
    g_XSN2[(size_t)row * 256 + c] = hh;
    g_XSN2[XSN_PLANE + (size_t)row * 256 + c] = ll;
}

// ================= HMMA flash attention, bf16 operands + cp.async double buffer =================
#define AST 40
__global__ void __launch_bounds__(256) attn_hmma()
{
    __shared__ __nv_bfloat16 Qs[128 * AST];
    __shared__ __nv_bfloat16 Ks[2][64 * AST];
    __shared__ __nv_bfloat16 Vhs[2][64 * AST];
    __shared__ __nv_bfloat16 Vls[2][64 * AST];

    const int tid = threadIdx.x;
    const int w = tid >> 5, lane = tid & 31;
    const int sb = blockIdx.z;
    const int h = blockIdx.y;
    const int n0 = blockIdx.x * 128;

    const __nv_bfloat16* Qg  = g_Qb + ((size_t)sb * NN + n0) * CC + h * DH;
    const __nv_bfloat16* Kg  = g_Kb + (size_t)sb * MM * CC + h * DH;
    const __nv_bfloat16* Vhg = g_Vh + (size_t)sb * MM * CC + h * DH;
    const __nv_bfloat16* Vlg = g_Vl + (size_t)sb * MM * CC + h * DH;

    // Q tile via cp.async (2 chunks/thread), grouped with stage-0 prefetch
    {
        int f0 = tid, f1 = tid + 256;
        int r0 = f0 >> 2, s0 = (f0 & 3) * 8;
        int r1 = f1 >> 2, s1 = (f1 & 3) * 8;
        cpasync16(smem_u32(&Qs[r0 * AST + s0]), Qg + (size_t)r0 * CC + s0);
        cpasync16(smem_u32(&Qs[r1 * AST + s1]), Qg + (size_t)r1 * CC + s1);
    }
    const int pr = tid >> 2, psg = (tid & 3) * 8;
    auto pf = [&](int mb, int st) {
        size_t src = (size_t)(mb * 64 + pr) * CC + psg;
        uint32_t doff = (pr * AST + psg) * 2;
        cpasync16(smem_u32(Ks[st])  + doff, Kg + src);
        cpasync16(smem_u32(Vhs[st]) + doff, Vhg + src);
        cpasync16(smem_u32(Vls[st]) + doff, Vlg + src);
        cpcommit();
    };
    pf(0, 0);

    const uint32_t qsb = smem_u32(Qs);
    uint32_t qf[2][4];
    float m0 = -1e30f, m1 = -1e30f, l0 = 0.f, l1 = 0.f;
    float oacc[4][4] = {};

    for (int mb = 0; mb < 16; mb++) {
        if (mb + 1 < 16) { pf(mb + 1, (mb + 1) & 1); cpwait<1>(); }
        else cpwait<0>();
        __syncthreads();
        if (mb == 0) {
#pragma unroll
            for (int ks = 0; ks < 2; ks++) {
                uint32_t off = (w * 16 + (lane & 15)) * (AST * 2) + ks * 32 + ((lane >> 4) & 1) * 16;
                ldm4(qf[ks], qsb + off);
            }
        }
        const int st = mb & 1;
        const uint32_t ksb = smem_u32(Ks[st]);
        const uint32_t vhb = smem_u32(Vhs[st]);
        const uint32_t vlb = smem_u32(Vls[st]);

        // ---- S = Q @ K^T ----
        float sacc[8][4] = {};
#pragma unroll
        for (int ks = 0; ks < 2; ks++) {
#pragma unroll
            for (int g = 0; g < 4; g++) {
                uint32_t off = (g * 16 + (lane & 7) + ((lane >> 4) & 1) * 8) * (AST * 2)
                               + ks * 32 + ((lane >> 3) & 1) * 16;
                uint32_t bk[4];
                ldm4(bk, ksb + off);
                mma16816(sacc[g * 2],     qf[ks], bk);
                mma16816(sacc[g * 2 + 1], qf[ks], bk + 2);
            }
        }

        // ---- online softmax ----
        float mx0 = -1e30f, mx1 = -1e30f;
#pragma unroll
        for (int j = 0; j < 8; j++) {
            mx0 = fmaxf(mx0, fmaxf(sacc[j][0], sacc[j][1]));
            mx1 = fmaxf(mx1, fmaxf(sacc[j][2], sacc[j][3]));
        }
        mx0 = fmaxf(mx0, __shfl_xor_sync(0xffffffffu, mx0, 1));
        mx0 = fmaxf(mx0, __shfl_xor_sync(0xffffffffu, mx0, 2));
        mx1 = fmaxf(mx1, __shfl_xor_sync(0xffffffffu, mx1, 1));
        mx1 = fmaxf(mx1, __shfl_xor_sync(0xffffffffu, mx1, 2));
        float mn0 = fmaxf(m0, mx0), mn1 = fmaxf(m1, mx1);
        float cf0 = __expf(m0 - mn0), cf1 = __expf(m1 - mn1);
        m0 = mn0; m1 = mn1;
        float s0 = 0.f, s1 = 0.f;
#pragma unroll
        for (int j = 0; j < 8; j++) {
            sacc[j][0] = __expf(sacc[j][0] - mn0);
            sacc[j][1] = __expf(sacc[j][1] - mn0);
            sacc[j][2] = __expf(sacc[j][2] - mn1);
            sacc[j][3] = __expf(sacc[j][3] - mn1);
            s0 += sacc[j][0] + sacc[j][1];
            s1 += sacc[j][2] + sacc[j][3];
        }
        s0 += __shfl_xor_sync(0xffffffffu, s0, 1);
        s0 += __shfl_xor_sync(0xffffffffu, s0, 2);
        s1 += __shfl_xor_sync(0xffffffffu, s1, 1);
        s1 += __shfl_xor_sync(0xffffffffu, s1, 2);
        l0 = l0 * cf0 + s0;
        l1 = l1 * cf1 + s1;
#pragma unroll
        for (int d = 0; d < 4; d++) {
            oacc[d][0] *= cf0; oacc[d][1] *= cf0;
            oacc[d][2] *= cf1; oacc[d][3] *= cf1;
        }

        // ---- O += P @ V (3-pass split; P split via Dekker) ----
#pragma unroll
        for (int t = 0; t < 4; t++) {
            uint32_t ph[4], pl[4];
            fsplit2(sacc[2 * t][0],     sacc[2 * t][1],     ph[0], pl[0]);
            fsplit2(sacc[2 * t][2],     sacc[2 * t][3],     ph[1], pl[1]);
            fsplit2(sacc[2 * t + 1][0], sacc[2 * t + 1][1], ph[2], pl[2]);
            fsplit2(sacc[2 * t + 1][2], sacc[2 * t + 1][3], ph[3], pl[3]);
            uint32_t r_base = (t * 16 + (lane & 7) + ((lane >> 3) & 1) * 8) * (AST * 2)
                              + ((lane >> 4) & 1) * 16;
            uint32_t vh0[4], vh1[4], vl0[4], vl1[4];
            ldm4t(vh0, vhb + r_base);
            ldm4t(vh1, vhb + r_base + 32);
            ldm4t(vl0, vlb + r_base);
            ldm4t(vl1, vlb + r_base + 32);
            mma16816(oacc[0], ph, vh0); mma16816(oacc[1], ph, vh0 + 2);
            mma16816(oacc[2], ph, vh1); mma16816(oacc[3], ph, vh1 + 2);
            mma16816(oacc[0], ph, vl0); mma16816(oacc[1], ph, vl0 + 2);
            mma16816(oacc[2], ph, vl1); mma16816(oacc[3], ph, vl1 + 2);
            mma16816(oacc[0], pl, vh0); mma16816(oacc[1], pl, vh0 + 2);
            mma16816(oacc[2], pl, vh1); mma16816(oacc[3], pl, vh1 + 2);
        }
        __syncthreads();
    }

    // ---- final normalize + hi/lo split store ----
    float inv0 = 1.f / l0, inv1 = 1.f / l1;
    size_t base0 = ((size_t)sb * NN + n0 + w * 16 + (lane >> 2)) * 256 + h * DH;
    size_t base1 = base0 + 8 * 256;
#pragma unroll
    for (int jt = 0; jt < 4; jt++) {
        int d0 = jt * 8 + (lane & 3) * 2;
        uint32_t h0p, l0p, h1p, l1p;
        fsplit2(oacc[jt][0] * inv0, oacc[jt][1] * inv0, h0p, l0p);
        fsplit2(oacc[jt][2] * inv1, oacc[jt][3] * inv1, h1p, l1p);
        *(uint32_t*)(g_AO2 + base0 + d0) = h0p;
        *(uint32_t*)(g_AO2 + AO_PLANE + base0 + d0) = l0p;
        *(uint32_t*)(g_AO2 + base1 + d0) = h1p;
        *(uint32_t*)(g_AO2 + AO_PLANE + base1 + d0) = l1p;
    }
}

// ================= launch =================
extern "C" void kernel_launch(void* const* d_in, const int* in_sizes, int n_in,
                              void* d_out, int out_size)
{
    const float* x0    = (const float*)d_in[0];
    const float* x1    = (const float*)d_in[1];
    const float* Wq    = (const float*)d_in[2];
    const float* Wkv   = (const float*)d_in[3];
    const float* Wproj = (const float*)d_in[4];
    const float* bproj = (const float*)d_in[5];
    const float* Wsr   = (const float*)d_in[6];
    const float* bsr   = (const float*)d_in[7];
    const float* lnw0  = (const float*)d_in[8];
    const float* lnb0  = (const float*)d_in[9];
    const float* lnw1  = (const float*)d_in[10];
    const float* lnb1  = (const float*)d_in[11];
    float* out = (float*)d_out;

    void *p_Wsr2, *p_XSN2, *p_Wkv2, *p_x2, *p_Wq2, *p_AO2, *p_Wpr2;
    void *p_XS, *p_Qb, *p_Kb, *p_Vh, *p_Vl;
    cudaGetSymbolAddress(&p_Wsr2, g_Wsr2);
    cudaGetSymbolAddress(&p_XSN2, g_XSN2);
    cudaGetSymbolAddress(&p_Wkv2, g_Wkv2);
    cudaGetSymbolAddress(&p_x2,   g_x2);
    cudaGetSymbolAddress(&p_Wq2,  g_Wq2);
    cudaGetSymbolAddress(&p_AO2,  g_AO2);
    cudaGetSymbolAddress(&p_Wpr2, g_Wpr2);
    cudaGetSymbolAddress(&p_XS,   g_XS);
    cudaGetSymbolAddress(&p_Qb,   g_Qb);
    cudaGetSymbolAddress(&p_Kb,   g_Kb);
    cudaGetSymbolAddress(&p_Vh,   g_Vh);
    cudaGetSymbolAddress(&p_Vl,   g_Vl);

    // 0) convert inputs/weights to bf16 hi/lo
    cvt_weights_kernel<<<1024, 256>>>(Wq, Wkv, Wproj, Wsr);
    cvt_x_kernel<<<8192, 256>>>(x0, x1);
    // 1) conv-as-GEMM (implicit im2col from g_x2, +bsr) -> g_XS [4096 x 256] fp32
    gemmT<0, true><<<dim3(64, 4), 128>>>(
        (const __nv_bfloat16*)p_x2, (size_t)X2_PLANE,
        (const __nv_bfloat16*)p_Wsr2, (size_t)262144,
        bsr, (float*)p_XS, nullptr, nullptr, nullptr, 1.f, 256, 1024);
    // 2) layernorm -> g_XSN2 (bf16 hi/lo)
    ln_kernel<<<4096, 256>>>(lnw0, lnb0, lnw1, lnb1);
    // 3) KV -> K bf16 + V hi/lo bf16 (direct epilogue split)
    gemmT<2, false><<<dim3(64, 8), 128>>>(
        (const __nv_bfloat16*)p_XSN2, (size_t)XSN_PLANE,
        (const __nv_bfloat16*)p_Wkv2, (size_t)131072,
        nullptr, nullptr, (__nv_bfloat16*)p_Kb, (__nv_bfloat16*)p_Vh, (__nv_bfloat16*)p_Vl,
        1.f, 512, 256);
    // 4) Q -> pre-scaled bf16
    gemmT<1, false><<<dim3(256, 4), 128>>>(
        (const __nv_bfloat16*)p_x2, (size_t)X2_PLANE,
        (const __nv_bfloat16*)p_Wq2, (size_t)65536,
        nullptr, nullptr, (__nv_bfloat16*)p_Qb, nullptr, nullptr,
        0.17677669529663687f, 256, 256);
    // 5) HMMA flash attention -> g_AO2 (bf16 hi/lo)
    attn_hmma<<<dim3(NN / 128, NH, NSTREAM * BB), 256>>>();
    // 6) out-proj (+bproj) -> d_out [16384 x 256] = (y0, y1)
    gemmT<0, false><<<dim3(256, 4), 128>>>(
        (const __nv_bfloat16*)p_AO2, (size_t)AO_PLANE,
        (const __nv_bfloat16*)p_Wpr2, (size_t)65536,
        bproj, out, nullptr, nullptr, nullptr, 1.f, 256, 256);
}